// round 1
// baseline (speedup 1.0000x reference)
#include <cuda_runtime.h>
#include <math.h>

#define H 128
#define CDIM 40
#define MAXN 100000
#define EPB 512

// scratch (device globals: allocation-free rule)
__device__ float g_agg[(size_t)MAXN * H];   // 51.2 MB
__device__ float g_h[(size_t)MAXN * H];     // 51.2 MB
__device__ float g_tmp[(size_t)MAXN * CDIM];// 16 MB

__global__ void zero_kernel(float* __restrict__ p, int n4) {
    int i = blockIdx.x * blockDim.x + threadIdx.x;
    if (i < n4) ((float4*)p)[i] = make_float4(0.f, 0.f, 0.f, 0.f);
}

// Segmented SPMM: agg[d] += w_e * h[s] for sorted edge_dst.
// One block = EPB contiguous edges; one thread per feature column.
// Register-accumulate per segment, atomic flush on dst change / block end.
template<int FW>
__global__ void spmm_kernel(const float* __restrict__ hin,
                            const int* __restrict__ src,
                            const int* __restrict__ dst,
                            const float* __restrict__ w,
                            float* __restrict__ agg, int E) {
    const int t = threadIdx.x;              // 0..FW-1
    const int base = blockIdx.x * EPB;
    if (base >= E) return;
    const int end = min(E, base + EPB);

    float acc = 0.f;
    int prev = dst[base];

    int e = base;
    for (; e + 4 <= end; e += 4) {
        const int4  s4 = *(const int4*)(src + e);
        const int4  d4 = *(const int4*)(dst + e);
        const float4 w4 = *(const float4*)(w + e);
        // 4 independent gathers in flight (MLP=4)
        float g0 = hin[(size_t)s4.x * FW + t];
        float g1 = hin[(size_t)s4.y * FW + t];
        float g2 = hin[(size_t)s4.z * FW + t];
        float g3 = hin[(size_t)s4.w * FW + t];
        if (d4.x != prev) { atomicAdd(&agg[(size_t)prev * FW + t], acc); acc = 0.f; prev = d4.x; }
        acc += w4.x * g0;
        if (d4.y != prev) { atomicAdd(&agg[(size_t)prev * FW + t], acc); acc = 0.f; prev = d4.y; }
        acc += w4.y * g1;
        if (d4.z != prev) { atomicAdd(&agg[(size_t)prev * FW + t], acc); acc = 0.f; prev = d4.z; }
        acc += w4.z * g2;
        if (d4.w != prev) { atomicAdd(&agg[(size_t)prev * FW + t], acc); acc = 0.f; prev = d4.w; }
        acc += w4.w * g3;
    }
    for (; e < end; ++e) { // tail (not hit for E=3.2M, kept for generality)
        int s = src[e], d = dst[e]; float we = w[e];
        float g = hin[(size_t)s * FW + t];
        if (d != prev) { atomicAdd(&agg[(size_t)prev * FW + t], acc); acc = 0.f; prev = d; }
        acc += we * g;
    }
    atomicAdd(&agg[(size_t)prev * FW + t], acc);
}

// C[N,128] = tanh(A[N,128] @ W[128,128]); classic smem-tiled SGEMM.
// BM=BN=128, BK=32, 256 threads, 8x8 register tile per thread.
__global__ __launch_bounds__(256) void gemm128_tanh(const float* __restrict__ A,
                                                    const float* __restrict__ W,
                                                    float* __restrict__ C, int N) {
    __shared__ float sA[32][128];  // [k][row] (transposed)
    __shared__ float sW[32][128];  // [k][col]
    const int tid = threadIdx.x;
    const int tr = tid >> 4;       // 0..15 -> rows tr*8..tr*8+7
    const int tc = tid & 15;       // 0..15 -> cols tc*8..tc*8+7
    const int rowBase = blockIdx.x * 128;

    float acc[8][8];
    #pragma unroll
    for (int i = 0; i < 8; ++i)
        #pragma unroll
        for (int j = 0; j < 8; ++j) acc[i][j] = 0.f;

    for (int kb = 0; kb < 128; kb += 32) {
        // load A tile: 128 rows x 32 k, transposed into sA[k][row]
        #pragma unroll
        for (int p = 0; p < 4; ++p) {
            int r = p * 32 + (tid >> 3);
            int c = (tid & 7) * 4;
            int gr = rowBase + r;
            float4 v = make_float4(0.f, 0.f, 0.f, 0.f);
            if (gr < N) v = *(const float4*)(A + (size_t)gr * 128 + kb + c);
            sA[c + 0][r] = v.x; sA[c + 1][r] = v.y;
            sA[c + 2][r] = v.z; sA[c + 3][r] = v.w;
        }
        // load W tile: 32 k x 128 cols
        #pragma unroll
        for (int p = 0; p < 4; ++p) {
            int r = p * 8 + (tid >> 5);
            int c = (tid & 31) * 4;
            float4 v = *(const float4*)(W + (size_t)(kb + r) * 128 + c);
            *(float4*)&sW[r][c] = v;
        }
        __syncthreads();

        #pragma unroll
        for (int k = 0; k < 32; ++k) {
            float a[8], b[8];
            *(float4*)(a)     = *(const float4*)&sA[k][tr * 8];
            *(float4*)(a + 4) = *(const float4*)&sA[k][tr * 8 + 4];
            *(float4*)(b)     = *(const float4*)&sW[k][tc * 8];
            *(float4*)(b + 4) = *(const float4*)&sW[k][tc * 8 + 4];
            #pragma unroll
            for (int i = 0; i < 8; ++i)
                #pragma unroll
                for (int j = 0; j < 8; ++j)
                    acc[i][j] += a[i] * b[j];
        }
        __syncthreads();
    }

    #pragma unroll
    for (int i = 0; i < 8; ++i) {
        int gr = rowBase + tr * 8 + i;
        if (gr < N) {
            float4 o0 = make_float4(tanhf(acc[i][0]), tanhf(acc[i][1]),
                                    tanhf(acc[i][2]), tanhf(acc[i][3]));
            float4 o1 = make_float4(tanhf(acc[i][4]), tanhf(acc[i][5]),
                                    tanhf(acc[i][6]), tanhf(acc[i][7]));
            *(float4*)(C + (size_t)gr * 128 + tc * 8)     = o0;
            *(float4*)(C + (size_t)gr * 128 + tc * 8 + 4) = o1;
        }
    }
}

// tmp[N,40] = A[N,128] @ W2[128,40]  (no activation; tanh comes after final spmm)
__global__ __launch_bounds__(160) void gemm40(const float* __restrict__ A,
                                              const float* __restrict__ W2,
                                              float* __restrict__ out, int N) {
    __shared__ float sW2[128 * 40];
    __shared__ float sAr[16][128];
    const int t = threadIdx.x;        // 0..159
    const int tx = t % 40;            // col
    const int ty = t / 40;            // 0..3 -> 4 rows each
    const int rowBase = blockIdx.x * 16;

    for (int i = t; i < 128 * 40; i += 160) sW2[i] = W2[i];
    for (int i = t; i < 16 * 128; i += 160) {
        int r = i >> 7, c = i & 127;
        int gr = rowBase + r;
        sAr[r][c] = (gr < N) ? A[(size_t)gr * 128 + c] : 0.f;
    }
    __syncthreads();

    float acc[4] = {0.f, 0.f, 0.f, 0.f};
    #pragma unroll 8
    for (int k = 0; k < 128; ++k) {
        float wv = sW2[k * 40 + tx];
        #pragma unroll
        for (int r = 0; r < 4; ++r)
            acc[r] += sAr[ty * 4 + r][k] * wv;
    }
    #pragma unroll
    for (int r = 0; r < 4; ++r) {
        int gr = rowBase + ty * 4 + r;
        if (gr < N) out[(size_t)gr * 40 + tx] = acc[r];
    }
}

__global__ void tanh_out_kernel(const float* __restrict__ in, float* __restrict__ out, int n) {
    int i = blockIdx.x * blockDim.x + threadIdx.x;
    if (i < n) out[i] = tanhf(in[i]);
}

extern "C" void kernel_launch(void* const* d_in, const int* in_sizes, int n_in,
                              void* d_out, int out_size) {
    const float* x    = (const float*)d_in[0];
    const int*   esrc = (const int*)d_in[1];
    const int*   edst = (const int*)d_in[2];
    const float* ew   = (const float*)d_in[3];
    const float* W0   = (const float*)d_in[4];
    const float* W1   = (const float*)d_in[5];
    const float* W2   = (const float*)d_in[6];
    float* out = (float*)d_out;

    const int N = in_sizes[0] / H;
    const int E = in_sizes[1];

    float *agg, *hb, *tmp;
    cudaGetSymbolAddress((void**)&agg, g_agg);
    cudaGetSymbolAddress((void**)&hb,  g_h);
    cudaGetSymbolAddress((void**)&tmp, g_tmp);

    const int n4_128 = N * H / 4;
    const int n4_40  = N * CDIM / 4;
    const int spmmBlocks = (E + EPB - 1) / EPB;
    const int gemmBlocks = (N + 127) / 128;

    // layer 1: h = tanh(spmm(x) @ W0)
    zero_kernel<<<(n4_128 + 255) / 256, 256>>>(agg, n4_128);
    spmm_kernel<H><<<spmmBlocks, H>>>(x, esrc, edst, ew, agg, E);
    gemm128_tanh<<<gemmBlocks, 256>>>(agg, W0, hb, N);

    // layer 2: h = tanh(spmm(h) @ W1)
    zero_kernel<<<(n4_128 + 255) / 256, 256>>>(agg, n4_128);
    spmm_kernel<H><<<spmmBlocks, H>>>(hb, esrc, edst, ew, agg, E);
    gemm128_tanh<<<gemmBlocks, 256>>>(agg, W1, hb, N);

    // layer 3 (reassociated): out = tanh(spmm(h @ W2))  -- 40-wide gather, 3.2x less traffic
    gemm40<<<(N + 15) / 16, 160>>>(hb, W2, tmp, N);
    zero_kernel<<<(n4_40 + 255) / 256, 256>>>(agg, n4_40);
    spmm_kernel<CDIM><<<spmmBlocks, CDIM>>>(tmp, esrc, edst, ew, agg, E);
    tanh_out_kernel<<<(N * CDIM + 255) / 256, 256>>>(agg, out, N * CDIM);
}

// round 2
// speedup vs baseline: 1.2594x; 1.2594x over previous
#include <cuda_runtime.h>
#include <math.h>

#define H 128
#define CDIM 40
#define MAXN 100000

// scratch (device globals: allocation-free rule)
__device__ float g_agg[(size_t)MAXN * H];    // 51.2 MB
__device__ float g_h[(size_t)MAXN * H];      // 51.2 MB
__device__ float g_tmp[(size_t)MAXN * CDIM]; // 16 MB
__device__ int   g_rowptr[MAXN + 1];

// row_ptr[i] = lower_bound(dst, E, i); dst is sorted.
__global__ void rowptr_kernel(const int* __restrict__ dst, int E, int N,
                              int* __restrict__ rp) {
    int i = blockIdx.x * blockDim.x + threadIdx.x;
    if (i > N) return;
    int lo = 0, hi = E;
    while (lo < hi) {
        int m = (lo + hi) >> 1;
        if (dst[m] < i) lo = m + 1; else hi = m;
    }
    rp[i] = lo;
}

// Atomic-free SPMM: one block per destination row (dst sorted -> contiguous
// edge range via row_ptr). Register accumulate, single store per element.
template<int FW, bool DOTANH>
__global__ void spmm_rows(const float* __restrict__ hin,
                          const int* __restrict__ src,
                          const float* __restrict__ w,
                          const int* __restrict__ rp,
                          float* __restrict__ out) {
    const int r = blockIdx.x;
    const int t = threadIdx.x;
    const int e0 = rp[r];
    const int e1 = rp[r + 1];
    if (t >= FW) return;

    float acc = 0.f;
    int e = e0;
    // 8 gathers in flight (MLP>=8)
    for (; e + 8 <= e1; e += 8) {
        int ss[8]; float ww[8], gg[8];
        #pragma unroll
        for (int j = 0; j < 8; ++j) { ss[j] = src[e + j]; ww[j] = w[e + j]; }
        #pragma unroll
        for (int j = 0; j < 8; ++j)
            gg[j] = __ldg(hin + (size_t)ss[j] * FW + t);
        #pragma unroll
        for (int j = 0; j < 8; ++j)
            acc += ww[j] * gg[j];
    }
    for (; e < e1; ++e)
        acc += w[e] * __ldg(hin + (size_t)src[e] * FW + t);

    float v = DOTANH ? tanhf(acc) : acc;
    out[(size_t)r * FW + t] = v;
}

// C[N,128] = tanh(A[N,128] @ W[128,128]); smem-tiled, f32x2 packed FMA.
// BM=BN=128, BK=32, 256 threads, 8x8 register tile (as 8x4 f32x2 pairs).
__global__ __launch_bounds__(256, 2) void gemm128_tanh(const float* __restrict__ A,
                                                       const float* __restrict__ W,
                                                       float* __restrict__ C, int N) {
    __shared__ float sA[32][128];  // [k][row] (transposed)
    __shared__ float sW[32][128];  // [k][col]
    const int tid = threadIdx.x;
    const int tr = tid >> 4;       // 0..15 -> rows tr*8..tr*8+7
    const int tc = tid & 15;       // 0..15 -> cols tc*8..tc*8+7
    const int rowBase = blockIdx.x * 128;

    unsigned long long acc2[8][4];
    #pragma unroll
    for (int i = 0; i < 8; ++i)
        #pragma unroll
        for (int j = 0; j < 4; ++j) acc2[i][j] = 0ull;

    for (int kb = 0; kb < 128; kb += 32) {
        #pragma unroll
        for (int p = 0; p < 4; ++p) {
            int r = p * 32 + (tid >> 3);
            int c = (tid & 7) * 4;
            int gr = rowBase + r;
            float4 v = make_float4(0.f, 0.f, 0.f, 0.f);
            if (gr < N) v = *(const float4*)(A + (size_t)gr * 128 + kb + c);
            sA[c + 0][r] = v.x; sA[c + 1][r] = v.y;
            sA[c + 2][r] = v.z; sA[c + 3][r] = v.w;
        }
        #pragma unroll
        for (int p = 0; p < 4; ++p) {
            int r = p * 8 + (tid >> 5);
            int c = (tid & 31) * 4;
            *(float4*)&sW[r][c] = *(const float4*)(W + (size_t)(kb + r) * 128 + c);
        }
        __syncthreads();

        #pragma unroll
        for (int k = 0; k < 32; ++k) {
            float a[8];
            unsigned long long b2[4];
            *(float4*)(a)     = *(const float4*)&sA[k][tr * 8];
            *(float4*)(a + 4) = *(const float4*)&sA[k][tr * 8 + 4];
            *(float4*)(&b2[0]) = *(const float4*)&sW[k][tc * 8];
            *(float4*)(&b2[2]) = *(const float4*)&sW[k][tc * 8 + 4];
            #pragma unroll
            for (int i = 0; i < 8; ++i) {
                unsigned long long a2;
                asm("mov.b64 %0, {%1, %1};" : "=l"(a2) : "f"(a[i]));
                #pragma unroll
                for (int j = 0; j < 4; ++j)
                    asm("fma.rn.f32x2 %0, %1, %2, %0;"
                        : "+l"(acc2[i][j]) : "l"(a2), "l"(b2[j]));
            }
        }
        __syncthreads();
    }

    #pragma unroll
    for (int i = 0; i < 8; ++i) {
        int gr = rowBase + tr * 8 + i;
        if (gr < N) {
            float2 p0 = *(float2*)&acc2[i][0];
            float2 p1 = *(float2*)&acc2[i][1];
            float2 p2 = *(float2*)&acc2[i][2];
            float2 p3 = *(float2*)&acc2[i][3];
            float4 o0 = make_float4(tanhf(p0.x), tanhf(p0.y), tanhf(p1.x), tanhf(p1.y));
            float4 o1 = make_float4(tanhf(p2.x), tanhf(p2.y), tanhf(p3.x), tanhf(p3.y));
            *(float4*)(C + (size_t)gr * 128 + tc * 8)     = o0;
            *(float4*)(C + (size_t)gr * 128 + tc * 8 + 4) = o1;
        }
    }
}

// tmp[N,40] = A[N,128] @ W2[128,40]  (no activation; tanh fused into final spmm)
__global__ __launch_bounds__(160) void gemm40(const float* __restrict__ A,
                                              const float* __restrict__ W2,
                                              float* __restrict__ out, int N) {
    __shared__ float sW2[128 * 40];
    __shared__ float sAr[16][128];
    const int t = threadIdx.x;
    const int tx = t % 40;
    const int ty = t / 40;
    const int rowBase = blockIdx.x * 16;

    for (int i = t; i < 128 * 40; i += 160) sW2[i] = W2[i];
    for (int i = t; i < 16 * 128; i += 160) {
        int r = i >> 7, c = i & 127;
        int gr = rowBase + r;
        sAr[r][c] = (gr < N) ? A[(size_t)gr * 128 + c] : 0.f;
    }
    __syncthreads();

    float acc[4] = {0.f, 0.f, 0.f, 0.f};
    #pragma unroll 8
    for (int k = 0; k < 128; ++k) {
        float wv = sW2[k * 40 + tx];
        #pragma unroll
        for (int r = 0; r < 4; ++r)
            acc[r] += sAr[ty * 4 + r][k] * wv;
    }
    #pragma unroll
    for (int r = 0; r < 4; ++r) {
        int gr = rowBase + ty * 4 + r;
        if (gr < N) out[(size_t)gr * 40 + tx] = acc[r];
    }
}

extern "C" void kernel_launch(void* const* d_in, const int* in_sizes, int n_in,
                              void* d_out, int out_size) {
    const float* x    = (const float*)d_in[0];
    const int*   esrc = (const int*)d_in[1];
    const int*   edst = (const int*)d_in[2];
    const float* ew   = (const float*)d_in[3];
    const float* W0   = (const float*)d_in[4];
    const float* W1   = (const float*)d_in[5];
    const float* W2   = (const float*)d_in[6];
    float* out = (float*)d_out;

    const int N = in_sizes[0] / H;
    const int E = in_sizes[1];

    float *agg, *hb, *tmp; int* rp;
    cudaGetSymbolAddress((void**)&agg, g_agg);
    cudaGetSymbolAddress((void**)&hb,  g_h);
    cudaGetSymbolAddress((void**)&tmp, g_tmp);
    cudaGetSymbolAddress((void**)&rp,  g_rowptr);

    const int gemmBlocks = (N + 127) / 128;

    // CSR row pointers from sorted edge_dst (same for all 3 layers)
    rowptr_kernel<<<(N + 256) / 256, 256>>>(edst, E, N, rp);

    // layer 1: h = tanh(spmm(x) @ W0)
    spmm_rows<H, false><<<N, H>>>(x, esrc, ew, rp, agg);
    gemm128_tanh<<<gemmBlocks, 256>>>(agg, W0, hb, N);

    // layer 2: h = tanh(spmm(h) @ W1)
    spmm_rows<H, false><<<N, H>>>(hb, esrc, ew, rp, agg);
    gemm128_tanh<<<gemmBlocks, 256>>>(agg, W1, hb, N);

    // layer 3 (reassociated): out = tanh(spmm(h @ W2)) -- 40-wide gather
    gemm40<<<(N + 15) / 16, 160>>>(hb, W2, tmp, N);
    spmm_rows<CDIM, true><<<N, 64>>>(tmp, esrc, ew, rp, out);
}

// round 3
// speedup vs baseline: 1.6443x; 1.3056x over previous
#include <cuda_runtime.h>
#include <math.h>

#define H 128
#define CDIM 40
#define MAXN 100000

// scratch (device globals: allocation-free rule); 16B-aligned for float4
__device__ __align__(16) float g_agg[(size_t)MAXN * H];    // 51.2 MB
__device__ __align__(16) float g_h[(size_t)MAXN * H];      // 51.2 MB
__device__ __align__(16) float g_tmp[(size_t)MAXN * CDIM]; // 16 MB
__device__ int g_rowptr[MAXN + 1];

// row_ptr[i] = lower_bound(dst, E, i); dst is sorted.
__global__ void rowptr_kernel(const int* __restrict__ dst, int E, int N,
                              int* __restrict__ rp) {
    int i = blockIdx.x * blockDim.x + threadIdx.x;
    if (i > N) return;
    int lo = 0, hi = E;
    while (lo < hi) {
        int m = (lo + hi) >> 1;
        if (dst[m] < i) lo = m + 1; else hi = m;
    }
    rp[i] = lo;
}

// Warp-per-row SPMM. 32 lanes x float4 = FW features (FW=128) or lanes<10 (FW=40).
// Edge metadata: coalesced chunk loads + shfl broadcast. Gather: 1 LDG.128/edge.
template<int FW, bool DOTANH>
__global__ __launch_bounds__(256) void spmm_warp(const float* __restrict__ hin,
                                                 const int* __restrict__ src,
                                                 const float* __restrict__ w,
                                                 const int* __restrict__ rp,
                                                 float* __restrict__ out, int N) {
    constexpr int ACTIVE = FW / 4;
    const int lane = threadIdx.x & 31;
    const int r = blockIdx.x * 8 + (threadIdx.x >> 5);
    if (r >= N) return;
    const int e0 = rp[r];
    const int e1 = rp[r + 1];

    float4 acc = make_float4(0.f, 0.f, 0.f, 0.f);

    for (int e = e0; e < e1; e += 32) {
        const int idx = e + lane;
        const bool valid = idx < e1;
        const int   s  = valid ? src[idx] : 0;
        const float wv = valid ? w[idx]   : 0.f;
        const int cnt = min(32, e1 - e);

        #pragma unroll
        for (int g = 0; g < 4; ++g) {
            if (g * 8 < cnt) {
                #pragma unroll
                for (int j = 0; j < 8; ++j) {
                    const int   sj = __shfl_sync(0xffffffffu, s,  g * 8 + j);
                    const float wj = __shfl_sync(0xffffffffu, wv, g * 8 + j);
                    if (lane < ACTIVE) {
                        const float4 gv = *(const float4*)(hin + (size_t)sj * FW + lane * 4);
                        acc.x += wj * gv.x; acc.y += wj * gv.y;
                        acc.z += wj * gv.z; acc.w += wj * gv.w;
                    }
                }
            }
        }
    }

    if (lane < ACTIVE) {
        float4 o = acc;
        if (DOTANH) {
            o.x = tanhf(o.x); o.y = tanhf(o.y);
            o.z = tanhf(o.z); o.w = tanhf(o.w);
        }
        *(float4*)(out + (size_t)r * FW + lane * 4) = o;
    }
}

// C[N,128] = tanh(A[N,128] @ W[128,128]); smem-tiled, f32x2 packed FMA.
__global__ __launch_bounds__(256, 2) void gemm128_tanh(const float* __restrict__ A,
                                                       const float* __restrict__ W,
                                                       float* __restrict__ C, int N) {
    __shared__ float sA[32][128];  // [k][row] (transposed)
    __shared__ float sW[32][128];  // [k][col]
    const int tid = threadIdx.x;
    const int tr = tid >> 4;
    const int tc = tid & 15;
    const int rowBase = blockIdx.x * 128;

    unsigned long long acc2[8][4];
    #pragma unroll
    for (int i = 0; i < 8; ++i)
        #pragma unroll
        for (int j = 0; j < 4; ++j) acc2[i][j] = 0ull;

    for (int kb = 0; kb < 128; kb += 32) {
        #pragma unroll
        for (int p = 0; p < 4; ++p) {
            int r = p * 32 + (tid >> 3);
            int c = (tid & 7) * 4;
            int gr = rowBase + r;
            float4 v = make_float4(0.f, 0.f, 0.f, 0.f);
            if (gr < N) v = *(const float4*)(A + (size_t)gr * 128 + kb + c);
            sA[c + 0][r] = v.x; sA[c + 1][r] = v.y;
            sA[c + 2][r] = v.z; sA[c + 3][r] = v.w;
        }
        #pragma unroll
        for (int p = 0; p < 4; ++p) {
            int r = p * 8 + (tid >> 5);
            int c = (tid & 31) * 4;
            *(float4*)&sW[r][c] = *(const float4*)(W + (size_t)(kb + r) * 128 + c);
        }
        __syncthreads();

        #pragma unroll
        for (int k = 0; k < 32; ++k) {
            float a[8];
            unsigned long long b2[4];
            *(float4*)(a)     = *(const float4*)&sA[k][tr * 8];
            *(float4*)(a + 4) = *(const float4*)&sA[k][tr * 8 + 4];
            *(float4*)(&b2[0]) = *(const float4*)&sW[k][tc * 8];
            *(float4*)(&b2[2]) = *(const float4*)&sW[k][tc * 8 + 4];
            #pragma unroll
            for (int i = 0; i < 8; ++i) {
                unsigned long long a2;
                asm("mov.b64 %0, {%1, %1};" : "=l"(a2) : "f"(a[i]));
                #pragma unroll
                for (int j = 0; j < 4; ++j)
                    asm("fma.rn.f32x2 %0, %1, %2, %0;"
                        : "+l"(acc2[i][j]) : "l"(a2), "l"(b2[j]));
            }
        }
        __syncthreads();
    }

    #pragma unroll
    for (int i = 0; i < 8; ++i) {
        int gr = rowBase + tr * 8 + i;
        if (gr < N) {
            float2 p0 = *(float2*)&acc2[i][0];
            float2 p1 = *(float2*)&acc2[i][1];
            float2 p2 = *(float2*)&acc2[i][2];
            float2 p3 = *(float2*)&acc2[i][3];
            float4 o0 = make_float4(tanhf(p0.x), tanhf(p0.y), tanhf(p1.x), tanhf(p1.y));
            float4 o1 = make_float4(tanhf(p2.x), tanhf(p2.y), tanhf(p3.x), tanhf(p3.y));
            *(float4*)(C + (size_t)gr * 128 + tc * 8)     = o0;
            *(float4*)(C + (size_t)gr * 128 + tc * 8 + 4) = o1;
        }
    }
}

// tmp[N,40] = A[N,128] @ W2[128,40]
__global__ __launch_bounds__(160) void gemm40(const float* __restrict__ A,
                                              const float* __restrict__ W2,
                                              float* __restrict__ out, int N) {
    __shared__ float sW2[128 * 40];
    __shared__ float sAr[16][128];
    const int t = threadIdx.x;
    const int tx = t % 40;
    const int ty = t / 40;
    const int rowBase = blockIdx.x * 16;

    for (int i = t; i < 128 * 40; i += 160) sW2[i] = W2[i];
    for (int i = t; i < 16 * 128; i += 160) {
        int r = i >> 7, c = i & 127;
        int gr = rowBase + r;
        sAr[r][c] = (gr < N) ? A[(size_t)gr * 128 + c] : 0.f;
    }
    __syncthreads();

    float acc[4] = {0.f, 0.f, 0.f, 0.f};
    #pragma unroll 8
    for (int k = 0; k < 128; ++k) {
        float wv = sW2[k * 40 + tx];
        #pragma unroll
        for (int r = 0; r < 4; ++r)
            acc[r] += sAr[ty * 4 + r][k] * wv;
    }
    #pragma unroll
    for (int r = 0; r < 4; ++r) {
        int gr = rowBase + ty * 4 + r;
        if (gr < N) out[(size_t)gr * 40 + tx] = acc[r];
    }
}

extern "C" void kernel_launch(void* const* d_in, const int* in_sizes, int n_in,
                              void* d_out, int out_size) {
    const float* x    = (const float*)d_in[0];
    const int*   esrc = (const int*)d_in[1];
    const int*   edst = (const int*)d_in[2];
    const float* ew   = (const float*)d_in[3];
    const float* W0   = (const float*)d_in[4];
    const float* W1   = (const float*)d_in[5];
    const float* W2   = (const float*)d_in[6];
    float* out = (float*)d_out;

    const int N = in_sizes[0] / H;
    const int E = in_sizes[1];

    float *agg, *hb, *tmp; int* rp;
    cudaGetSymbolAddress((void**)&agg, g_agg);
    cudaGetSymbolAddress((void**)&hb,  g_h);
    cudaGetSymbolAddress((void**)&tmp, g_tmp);
    cudaGetSymbolAddress((void**)&rp,  g_rowptr);

    const int gemmBlocks = (N + 127) / 128;
    const int spmmBlocks = (N + 7) / 8;

    rowptr_kernel<<<(N + 256) / 256, 256>>>(edst, E, N, rp);

    // layer 1: h = tanh(spmm(x) @ W0)
    spmm_warp<H, false><<<spmmBlocks, 256>>>(x, esrc, ew, rp, agg, N);
    gemm128_tanh<<<gemmBlocks, 256>>>(agg, W0, hb, N);

    // layer 2: h = tanh(spmm(h) @ W1)
    spmm_warp<H, false><<<spmmBlocks, 256>>>(hb, esrc, ew, rp, agg, N);
    gemm128_tanh<<<gemmBlocks, 256>>>(agg, W1, hb, N);

    // layer 3 (reassociated): out = tanh(spmm(h @ W2)) -- 40-wide gather
    gemm40<<<(N + 15) / 16, 160>>>(hb, W2, tmp, N);
    spmm_warp<CDIM, true><<<spmmBlocks, 256>>>(tmp, esrc, ew, rp, out, N);
}

// round 4
// speedup vs baseline: 1.9296x; 1.1735x over previous
#include <cuda_runtime.h>
#include <cuda_fp16.h>
#include <math.h>

#define H 128
#define CDIM 40
#define TMPW 64   /* padded half-row stride for layer-3 gather (128B) */
#define MAXN 100000

// scratch (device globals: allocation-free rule)
__device__ __align__(16) float  g_agg[(size_t)MAXN * H];     // 51.2 MB (f32 spmm out / gemm in)
__device__ __align__(16) __half g_xh [(size_t)MAXN * H];     // 25.6 MB
__device__ __align__(16) __half g_hb [(size_t)MAXN * H];     // 25.6 MB
__device__ __align__(16) __half g_tmp[(size_t)MAXN * TMPW];  // 12.8 MB
__device__ int g_rowptr[MAXN + 1];

// row_ptr[i] = lower_bound(dst, E, i); dst is sorted.
__global__ void rowptr_kernel(const int* __restrict__ dst, int E, int N,
                              int* __restrict__ rp) {
    int i = blockIdx.x * blockDim.x + threadIdx.x;
    if (i > N) return;
    int lo = 0, hi = E;
    while (lo < hi) {
        int m = (lo + hi) >> 1;
        if (dst[m] < i) lo = m + 1; else hi = m;
    }
    rp[i] = lo;
}

// f32 -> f16 convert (for layer-1 input x)
__global__ void f2h_kernel(const float* __restrict__ in, __half* __restrict__ out, int n2) {
    int i = blockIdx.x * blockDim.x + threadIdx.x;
    if (i < n2) {
        float2 v = ((const float2*)in)[i];
        ((__half2*)out)[i] = __floats2half2_rn(v.x, v.y);
    }
}

// Warp-per-row SPMM, fp16 payload, f32 accumulate. 128 features:
// 32 lanes x uint2 (4 halves) = 256B/edge = 2 L1 wavefronts.
__global__ __launch_bounds__(256) void spmm_h128(const __half* __restrict__ hin,
                                                 const int* __restrict__ src,
                                                 const float* __restrict__ w,
                                                 const int* __restrict__ rp,
                                                 float* __restrict__ out, int N) {
    const int lane = threadIdx.x & 31;
    const int r = blockIdx.x * 8 + (threadIdx.x >> 5);
    if (r >= N) return;
    const int e0 = rp[r];
    const int e1 = rp[r + 1];

    float4 acc = make_float4(0.f, 0.f, 0.f, 0.f);

    for (int e = e0; e < e1; e += 32) {
        const int idx = e + lane;
        const bool valid = idx < e1;
        const int   s  = valid ? src[idx] : 0;
        const float wv = valid ? w[idx]   : 0.f;
        const int cnt = e1 - e;

        #pragma unroll
        for (int g = 0; g < 4; ++g) {
            if (g * 8 < cnt) {
                #pragma unroll
                for (int j = 0; j < 8; ++j) {
                    const int   sj = __shfl_sync(0xffffffffu, s,  g * 8 + j);
                    const float wj = __shfl_sync(0xffffffffu, wv, g * 8 + j);
                    const uint2 gv = *(const uint2*)(hin + (size_t)sj * H + lane * 4);
                    const float2 f0 = __half22float2(*(const __half2*)&gv.x);
                    const float2 f1 = __half22float2(*(const __half2*)&gv.y);
                    acc.x += wj * f0.x; acc.y += wj * f0.y;
                    acc.z += wj * f1.x; acc.w += wj * f1.y;
                }
            }
        }
    }

    *(float4*)(out + (size_t)r * H + lane * 4) = acc;
}

// Layer-3 SPMM: fp16 payload (40 feats, rows padded to 64 halves = 128B),
// 20 active lanes x half2 = 1 L1 wavefront/edge. tanh fused; f32 output.
__global__ __launch_bounds__(256) void spmm_h40_tanh(const __half* __restrict__ hin,
                                                     const int* __restrict__ src,
                                                     const float* __restrict__ w,
                                                     const int* __restrict__ rp,
                                                     float* __restrict__ out, int N) {
    const int lane = threadIdx.x & 31;
    const int r = blockIdx.x * 8 + (threadIdx.x >> 5);
    if (r >= N) return;
    const int e0 = rp[r];
    const int e1 = rp[r + 1];

    float2 acc = make_float2(0.f, 0.f);

    for (int e = e0; e < e1; e += 32) {
        const int idx = e + lane;
        const bool valid = idx < e1;
        const int   s  = valid ? src[idx] : 0;
        const float wv = valid ? w[idx]   : 0.f;
        const int cnt = e1 - e;

        #pragma unroll
        for (int g = 0; g < 4; ++g) {
            if (g * 8 < cnt) {
                #pragma unroll
                for (int j = 0; j < 8; ++j) {
                    const int   sj = __shfl_sync(0xffffffffu, s,  g * 8 + j);
                    const float wj = __shfl_sync(0xffffffffu, wv, g * 8 + j);
                    if (lane < 20) {
                        const __half2 gv = *(const __half2*)(hin + (size_t)sj * TMPW + lane * 2);
                        const float2 f = __half22float2(gv);
                        acc.x += wj * f.x; acc.y += wj * f.y;
                    }
                }
            }
        }
    }

    if (lane < 20) {
        float2 o = make_float2(tanhf(acc.x), tanhf(acc.y));
        *(float2*)(out + (size_t)r * CDIM + lane * 2) = o;
    }
}

// C[N,128](half) = tanh(A[N,128](f32) @ W[128,128](f32)); f32x2 packed FMA.
__global__ __launch_bounds__(256, 2) void gemm128_tanh_h(const float* __restrict__ A,
                                                         const float* __restrict__ W,
                                                         __half* __restrict__ C, int N) {
    __shared__ float sA[32][128];  // [k][row] (transposed)
    __shared__ float sW[32][128];  // [k][col]
    const int tid = threadIdx.x;
    const int tr = tid >> 4;
    const int tc = tid & 15;
    const int rowBase = blockIdx.x * 128;

    unsigned long long acc2[8][4];
    #pragma unroll
    for (int i = 0; i < 8; ++i)
        #pragma unroll
        for (int j = 0; j < 4; ++j) acc2[i][j] = 0ull;

    for (int kb = 0; kb < 128; kb += 32) {
        #pragma unroll
        for (int p = 0; p < 4; ++p) {
            int r = p * 32 + (tid >> 3);
            int c = (tid & 7) * 4;
            int gr = rowBase + r;
            float4 v = make_float4(0.f, 0.f, 0.f, 0.f);
            if (gr < N) v = *(const float4*)(A + (size_t)gr * 128 + kb + c);
            sA[c + 0][r] = v.x; sA[c + 1][r] = v.y;
            sA[c + 2][r] = v.z; sA[c + 3][r] = v.w;
        }
        #pragma unroll
        for (int p = 0; p < 4; ++p) {
            int r = p * 8 + (tid >> 5);
            int c = (tid & 31) * 4;
            *(float4*)&sW[r][c] = *(const float4*)(W + (size_t)(kb + r) * 128 + c);
        }
        __syncthreads();

        #pragma unroll
        for (int k = 0; k < 32; ++k) {
            float a[8];
            unsigned long long b2[4];
            *(float4*)(a)     = *(const float4*)&sA[k][tr * 8];
            *(float4*)(a + 4) = *(const float4*)&sA[k][tr * 8 + 4];
            *(float4*)(&b2[0]) = *(const float4*)&sW[k][tc * 8];
            *(float4*)(&b2[2]) = *(const float4*)&sW[k][tc * 8 + 4];
            #pragma unroll
            for (int i = 0; i < 8; ++i) {
                unsigned long long a2;
                asm("mov.b64 %0, {%1, %1};" : "=l"(a2) : "f"(a[i]));
                #pragma unroll
                for (int j = 0; j < 4; ++j)
                    asm("fma.rn.f32x2 %0, %1, %2, %0;"
                        : "+l"(acc2[i][j]) : "l"(a2), "l"(b2[j]));
            }
        }
        __syncthreads();
    }

    #pragma unroll
    for (int i = 0; i < 8; ++i) {
        int gr = rowBase + tr * 8 + i;
        if (gr < N) {
            uint4 o;
            #pragma unroll
            for (int j = 0; j < 4; ++j) {
                float2 p = *(float2*)&acc2[i][j];
                __half2 h = __floats2half2_rn(tanhf(p.x), tanhf(p.y));
                ((unsigned*)&o)[j] = *(unsigned*)&h;
            }
            *(uint4*)(C + (size_t)gr * 128 + tc * 8) = o;
        }
    }
}

// tmp[N, pad64](half) = A[N,128](half) @ W2[128,40](f32)
__global__ __launch_bounds__(160) void gemm40_h(const __half* __restrict__ A,
                                                const float* __restrict__ W2,
                                                __half* __restrict__ out, int N) {
    __shared__ float sW2[128 * 40];
    __shared__ float sAr[16][128];
    const int t = threadIdx.x;
    const int tx = t % 40;
    const int ty = t / 40;
    const int rowBase = blockIdx.x * 16;

    for (int i = t; i < 128 * 40; i += 160) sW2[i] = W2[i];
    for (int i = t; i < 16 * 64; i += 160) {   // 16 rows x 64 half2
        int r = i >> 6, c = (i & 63) * 2;
        int gr = rowBase + r;
        float2 v = make_float2(0.f, 0.f);
        if (gr < N) v = __half22float2(*(const __half2*)(A + (size_t)gr * 128 + c));
        sAr[r][c] = v.x; sAr[r][c + 1] = v.y;
    }
    __syncthreads();

    float acc[4] = {0.f, 0.f, 0.f, 0.f};
    #pragma unroll 8
    for (int k = 0; k < 128; ++k) {
        float wv = sW2[k * 40 + tx];
        #pragma unroll
        for (int r = 0; r < 4; ++r)
            acc[r] += sAr[ty * 4 + r][k] * wv;
    }
    #pragma unroll
    for (int r = 0; r < 4; ++r) {
        int gr = rowBase + ty * 4 + r;
        if (gr < N) out[(size_t)gr * TMPW + tx] = __float2half(acc[r]);
    }
}

extern "C" void kernel_launch(void* const* d_in, const int* in_sizes, int n_in,
                              void* d_out, int out_size) {
    const float* x    = (const float*)d_in[0];
    const int*   esrc = (const int*)d_in[1];
    const int*   edst = (const int*)d_in[2];
    const float* ew   = (const float*)d_in[3];
    const float* W0   = (const float*)d_in[4];
    const float* W1   = (const float*)d_in[5];
    const float* W2   = (const float*)d_in[6];
    float* out = (float*)d_out;

    const int N = in_sizes[0] / H;
    const int E = in_sizes[1];

    float* agg; __half *xh, *hb, *tmp; int* rp;
    cudaGetSymbolAddress((void**)&agg, g_agg);
    cudaGetSymbolAddress((void**)&xh,  g_xh);
    cudaGetSymbolAddress((void**)&hb,  g_hb);
    cudaGetSymbolAddress((void**)&tmp, g_tmp);
    cudaGetSymbolAddress((void**)&rp,  g_rowptr);

    const int gemmBlocks = (N + 127) / 128;
    const int spmmBlocks = (N + 7) / 8;

    rowptr_kernel<<<(N + 256) / 256, 256>>>(edst, E, N, rp);
    f2h_kernel<<<(N * H / 2 + 255) / 256, 256>>>(x, xh, N * H / 2);

    // layer 1: h = tanh(spmm(x) @ W0)
    spmm_h128<<<spmmBlocks, 256>>>(xh, esrc, ew, rp, agg, N);
    gemm128_tanh_h<<<gemmBlocks, 256>>>(agg, W0, hb, N);

    // layer 2: h = tanh(spmm(h) @ W1)
    spmm_h128<<<spmmBlocks, 256>>>(hb, esrc, ew, rp, agg, N);
    gemm128_tanh_h<<<gemmBlocks, 256>>>(agg, W1, hb, N);

    // layer 3 (reassociated): out = tanh(spmm(h @ W2)) -- 40-wide fp16 gather
    gemm40_h<<<(N + 15) / 16, 160>>>(hb, W2, tmp, N);
    spmm_h40_tanh<<<spmmBlocks, 256>>>(tmp, esrc, ew, rp, out, N);
}